// round 15
// baseline (speedup 1.0000x reference)
#include <cuda_runtime.h>
#include <cstdint>

// Problem constants (from reference)
#define NPTS 20000
#define NV   6
#define NP   64
#define ND   32

#define W_F  1600.0f
#define H_F  928.0f
#define EPSF 1e-5f
#define FULLMASK 0xffffffffu

// Output layout (flatten + concat, float32):
//   xy_proj : (N, V, D, 2)  -> 7,680,000
//   mask    : (N, V, D)     -> 3,840,000
//   corr    : (N, V, P)     -> 7,680,000

__global__ __launch_bounds__(64) void boxcorr_kernel(
    const float* __restrict__ points,      // (N,3): [img_id, x, y]
    const float* __restrict__ trans_mats,  // (V,V,4,4)
    const float4* __restrict__ rois,       // (V,P,4) as float4
    float* __restrict__ out)
{
    // 10000 blocks x 2 warps = 20000 warps = NPTS exactly: no bounds guard.
    const int n    = blockIdx.x * 2 + (threadIdx.x >> 5);  // one warp per point
    const int lane = threadIdx.x & 31;

    // Point data (uniform across warp) — loaded ONCE per point
    const float idf = __ldg(points + n * 3 + 0);
    const float x   = __ldg(points + n * 3 + 1);
    const float y   = __ldg(points + n * 3 + 2);
    const int   id  = (int)idf;

    // LID depth for this lane (bit-exact vs reference)
    const float binsz = (float)(69.5 / 1056.0);
    const float fi = (float)lane;
    const float d  = __fadd_rn(0.5f, __fmul_rn(__fmul_rn(binsz, fi), __fadd_rn(fi, 1.0f)));
    const float xd = __fmul_rn(x, d);
    const float yd = __fmul_rn(y, d);

    float* maskout = out + (size_t)NPTS * NV * ND * 2;
    float* corrout = out + (size_t)NPTS * NV * ND * 2 + (size_t)NPTS * NV * ND;

#pragma unroll
    for (int v = 0; v < NV; ++v) {
        // 4x4 transform rows 0..2 for (v, img_id) — uniform LDG.128, L1 hot
        const float4* Tm = (const float4*)(trans_mats + (v * NV + id) * 16);
        const float4 T0 = __ldg(Tm + 0);
        const float4 T1 = __ldg(Tm + 1);
        const float4 T2 = __ldg(Tm + 2);

        // proj = T @ [x*d, y*d, d, 1], ascending-j fma accumulation (matches XLA)
        float px = __fmul_rn(T0.x, xd);
        px = __fmaf_rn(T0.y, yd, px);
        px = __fmaf_rn(T0.z, d,  px);
        px = __fadd_rn(px, T0.w);

        float py = __fmul_rn(T1.x, xd);
        py = __fmaf_rn(T1.y, yd, py);
        py = __fmaf_rn(T1.z, d,  py);
        py = __fadd_rn(py, T1.w);

        float z = __fmul_rn(T2.x, xd);
        z = __fmaf_rn(T2.y, yd, z);
        z = __fmaf_rn(T2.z, d,  z);
        z = __fadd_rn(z, T2.w);

        const float zc = fmaxf(z, EPSF);
        const float xq = __fdiv_rn(px, zc);
        const float yq = __fdiv_rn(py, zc);

        const bool valid = (z > EPSF) & (xq >= 0.0f) & (xq < W_F)
                                      & (yq >= 0.0f) & (yq < H_F);

        // ---- write xy_proj + mask (coalesced per warp) ----
        const size_t dbase = ((size_t)n * NV + v) * ND;
        ((float2*)out)[dbase + lane] = make_float2(xq, yq);
        maskout[dbase + lane] = valid ? 1.0f : 0.0f;

        unsigned mm0 = 0u, mm1 = 0u;
        const unsigned vmask = __ballot_sync(FULLMASK, valid);
        if (vmask) {   // warp-uniform: skip all corr work if no valid depth
            // warp bbox over VALID points (uint order == float order for >=0)
            const unsigned xb = __float_as_uint(xq) & 0x7fffffffu;
            const unsigned yb = __float_as_uint(yq) & 0x7fffffffu;
            const float minx = __uint_as_float(__reduce_min_sync(FULLMASK, valid ? xb : 0x7f800000u));
            const float maxx = __uint_as_float(__reduce_max_sync(FULLMASK, valid ? xb : 0u));
            const float miny = __uint_as_float(__reduce_min_sync(FULLMASK, valid ? yb : 0x7f800000u));
            const float maxy = __uint_as_float(__reduce_max_sync(FULLMASK, valid ? yb : 0u));

            // candidate ROI mask: lane tests ROI[lane], ROI[lane+32] vs bbox
            const float4* Rv = rois + v * NP;
            const float4 ra = __ldg(Rv + lane);
            const float4 rb = __ldg(Rv + lane + 32);
            const bool ca = (maxx > ra.x) & (minx < ra.z) & (maxy > ra.y) & (miny < ra.w);
            const bool cb = (maxx > rb.x) & (minx < rb.z) & (maxy > rb.y) & (miny < rb.w);
            unsigned b0 = __ballot_sync(FULLMASK, ca);
            unsigned b1 = __ballot_sync(FULLMASK, cb);

            // exact test only for candidates; ballot collapses the depth dim
            while (b0) {
                const int p = __ffs(b0) - 1;
                b0 &= b0 - 1;
                const float4 r = __ldg(Rv + p);          // uniform LDG, L1 hot
                const bool inb = valid & (xq > r.x) & (xq < r.z)
                                       & (yq > r.y) & (yq < r.w);
                if (__ballot_sync(FULLMASK, inb)) mm0 |= (1u << p);
            }
            while (b1) {
                const int p = __ffs(b1) - 1;
                b1 &= b1 - 1;
                const float4 r = __ldg(Rv + p + 32);
                const bool inb = valid & (xq > r.x) & (xq < r.z)
                                       & (yq > r.y) & (yq < r.w);
                if (__ballot_sync(FULLMASK, inb)) mm1 |= (1u << p);
            }
        }

        // corr[n,v,p]: lane writes roi `lane` and roi `lane+32` (coalesced)
        const size_t cbase = dbase * 2;    // ((n*NV+v)*64)
        corrout[cbase + lane]      = ((mm0 >> lane) & 1u) ? 1.0f : 0.0f;
        corrout[cbase + 32 + lane] = ((mm1 >> lane) & 1u) ? 1.0f : 0.0f;
    }
}

extern "C" void kernel_launch(void* const* d_in, const int* in_sizes, int n_in,
                              void* d_out, int out_size)
{
    const float*  points = (const float*)d_in[0];   // (N,3)
    const float*  trans  = (const float*)d_in[1];   // (V,V,4,4)
    const float4* rois   = (const float4*)d_in[2];  // (V,P,4)
    float* out = (float*)d_out;

    const int blocks = NPTS / 2;                    // 2 warps/block -> 10000 blocks
    boxcorr_kernel<<<blocks, 64>>>(points, trans, rois, out);
}

// round 16
// speedup vs baseline: 1.0152x; 1.0152x over previous
#include <cuda_runtime.h>
#include <cstdint>

// Problem constants (from reference)
#define NPTS 20000
#define NV   6
#define NP   64
#define ND   32

#define W_F  1600.0f
#define H_F  928.0f
#define EPSF 1e-5f
#define FULLMASK 0xffffffffu

// Output layout (flatten + concat, float32):
//   xy_proj : (N, V, D, 2)  -> 7,680,000
//   mask    : (N, V, D)     -> 3,840,000
//   corr    : (N, V, P)     -> 7,680,000

// Refined reciprocal: rcp.approx (~2^-22.6) + 2 Newton steps -> correctly
// rounded 1/b for normal b (our zc in [1e-5, ~1e2], no specials).
__device__ __forceinline__ float frcp_refined(float b) {
    float r;
    asm("rcp.approx.ftz.f32 %0, %1;" : "=f"(r) : "f"(b));
    float e = __fmaf_rn(-b, r, 1.0f);
    r = __fmaf_rn(r, e, r);
    e = __fmaf_rn(-b, r, 1.0f);
    r = __fmaf_rn(r, e, r);
    return r;
}

// Markstein correctly-rounded quotient given correctly-rounded reciprocal r.
__device__ __forceinline__ float fdiv_cr(float a, float b, float r) {
    float q = __fmul_rn(a, r);
    float e = __fmaf_rn(-b, q, a);
    return __fmaf_rn(e, r, q);
}

__global__ __launch_bounds__(128) void boxcorr_kernel(
    const float* __restrict__ points,      // (N,3): [img_id, x, y]
    const float* __restrict__ trans_mats,  // (V,V,4,4)
    const float4* __restrict__ rois,       // (V,P,4) as float4
    float* __restrict__ out)
{
    const int warpid = blockIdx.x * 4 + (threadIdx.x >> 5);  // one warp per point
    const int lane   = threadIdx.x & 31;
    if (warpid >= NPTS) return;
    const int n = warpid;

    // Point data (uniform across warp) — loaded ONCE per point
    const float idf = __ldg(points + n * 3 + 0);
    const float x   = __ldg(points + n * 3 + 1);
    const float y   = __ldg(points + n * 3 + 2);
    const int   id  = (int)idf;

    // LID depth for this lane (bit-exact vs reference)
    const float binsz = (float)(69.5 / 1056.0);
    const float fi = (float)lane;
    const float d  = __fadd_rn(0.5f, __fmul_rn(__fmul_rn(binsz, fi), __fadd_rn(fi, 1.0f)));
    const float xd = __fmul_rn(x, d);
    const float yd = __fmul_rn(y, d);

    float* maskout = out + (size_t)NPTS * NV * ND * 2;
    float* corrout = out + (size_t)NPTS * NV * ND * 2 + (size_t)NPTS * NV * ND;

#pragma unroll
    for (int v = 0; v < NV; ++v) {
        // 4x4 transform rows 0..2 for (v, img_id) — uniform LDG.128, L1 hot
        const float4* Tm = (const float4*)(trans_mats + (v * NV + id) * 16);
        const float4 T0 = __ldg(Tm + 0);
        const float4 T1 = __ldg(Tm + 1);
        const float4 T2 = __ldg(Tm + 2);

        // proj = T @ [x*d, y*d, d, 1], ascending-j fma accumulation (matches XLA)
        float px = __fmul_rn(T0.x, xd);
        px = __fmaf_rn(T0.y, yd, px);
        px = __fmaf_rn(T0.z, d,  px);
        px = __fadd_rn(px, T0.w);

        float py = __fmul_rn(T1.x, xd);
        py = __fmaf_rn(T1.y, yd, py);
        py = __fmaf_rn(T1.z, d,  py);
        py = __fadd_rn(py, T1.w);

        float z = __fmul_rn(T2.x, xd);
        z = __fmaf_rn(T2.y, yd, z);
        z = __fmaf_rn(T2.z, d,  z);
        z = __fadd_rn(z, T2.w);

        const float zc = fmaxf(z, EPSF);
        // Shared correctly-rounded reciprocal; two Markstein quotients
        const float rz = frcp_refined(zc);
        const float xq = fdiv_cr(px, zc, rz);
        const float yq = fdiv_cr(py, zc, rz);

        const bool valid = (z > EPSF) & (xq >= 0.0f) & (xq < W_F)
                                      & (yq >= 0.0f) & (yq < H_F);

        // ---- write xy_proj + mask (coalesced per warp) ----
        const size_t dbase = ((size_t)n * NV + v) * ND;
        ((float2*)out)[dbase + lane] = make_float2(xq, yq);
        maskout[dbase + lane] = valid ? 1.0f : 0.0f;

        unsigned mm0 = 0u, mm1 = 0u;
        const unsigned vmask = __ballot_sync(FULLMASK, valid);
        if (vmask) {   // warp-uniform: skip all corr work if no valid depth
            // warp bbox over VALID points (uint order == float order for >=0)
            const unsigned xb = __float_as_uint(xq) & 0x7fffffffu;
            const unsigned yb = __float_as_uint(yq) & 0x7fffffffu;
            const float minx = __uint_as_float(__reduce_min_sync(FULLMASK, valid ? xb : 0x7f800000u));
            const float maxx = __uint_as_float(__reduce_max_sync(FULLMASK, valid ? xb : 0u));
            const float miny = __uint_as_float(__reduce_min_sync(FULLMASK, valid ? yb : 0x7f800000u));
            const float maxy = __uint_as_float(__reduce_max_sync(FULLMASK, valid ? yb : 0u));

            // candidate ROI mask: lane tests ROI[lane], ROI[lane+32] vs bbox
            const float4* Rv = rois + v * NP;
            const float4 ra = __ldg(Rv + lane);
            const float4 rb = __ldg(Rv + lane + 32);
            const bool ca = (maxx > ra.x) & (minx < ra.z) & (maxy > ra.y) & (miny < ra.w);
            const bool cb = (maxx > rb.x) & (minx < rb.z) & (maxy > rb.y) & (miny < rb.w);
            unsigned b0 = __ballot_sync(FULLMASK, ca);
            unsigned b1 = __ballot_sync(FULLMASK, cb);

            // exact test only for candidates; ballot collapses the depth dim
            while (b0) {
                const int p = __ffs(b0) - 1;
                b0 &= b0 - 1;
                const float4 r = __ldg(Rv + p);          // uniform LDG, L1 hot
                const bool inb = valid & (xq > r.x) & (xq < r.z)
                                       & (yq > r.y) & (yq < r.w);
                if (__ballot_sync(FULLMASK, inb)) mm0 |= (1u << p);
            }
            while (b1) {
                const int p = __ffs(b1) - 1;
                b1 &= b1 - 1;
                const float4 r = __ldg(Rv + p + 32);
                const bool inb = valid & (xq > r.x) & (xq < r.z)
                                       & (yq > r.y) & (yq < r.w);
                if (__ballot_sync(FULLMASK, inb)) mm1 |= (1u << p);
            }
        }

        // corr[n,v,p]: lane writes elements 2*lane, 2*lane+1 as one STG.64
        const unsigned sel = (lane < 16) ? mm0 : mm1;
        const int sh = (lane * 2) & 31;
        float2 c;
        c.x = ((sel >> sh) & 1u)       ? 1.0f : 0.0f;
        c.y = ((sel >> (sh + 1)) & 1u) ? 1.0f : 0.0f;
        ((float2*)(corrout + dbase * 2))[lane] = c;
    }
}

extern "C" void kernel_launch(void* const* d_in, const int* in_sizes, int n_in,
                              void* d_out, int out_size)
{
    const float*  points = (const float*)d_in[0];   // (N,3)
    const float*  trans  = (const float*)d_in[1];   // (V,V,4,4)
    const float4* rois   = (const float4*)d_in[2];  // (V,P,4)
    float* out = (float*)d_out;

    const int total_warps = NPTS;                   // one warp per point
    const int blocks = (total_warps + 3) / 4;       // 4 warps/block -> 5000 blocks
    boxcorr_kernel<<<blocks, 128>>>(points, trans, rois, out);
}